// round 16
// baseline (speedup 1.0000x reference)
#include <cuda_runtime.h>

// Problem constants (fixed shapes from reference setup_inputs)
#define BB   8
#define CC   128
#define HH   128
#define WW   128
#define HO   256            // HH * 2
#define WO   256            // WW * 2
#define HW   (HH * WW)      // 16384
#define HOWO (HO * WO)      // 65536

__global__ __launch_bounds__(256)
void LaU_upsample_kernel(const float* __restrict__ in,
                         const float* __restrict__ offx,
                         const float* __restrict__ offy,
                         float* __restrict__ out)
{
    const int idx = blockIdx.x * 256 + threadIdx.x;   // 0 .. B*HO*WO-1
    const int wo = idx & (WO - 1);
    const int ho = (idx >> 8) & (HO - 1);
    const int b  = idx >> 16;

    const int so = b * HOWO + ho * WO + wo;           // spatial index (offsets)

    // sample coordinates (shared by all 128 channels)
    const float x = 0.5f * (float)wo + offx[so];
    const float y = 0.5f * (float)ho + offy[so];

    const float x0f = floorf(x);
    const float y0f = floorf(y);
    const float wx = x - x0f;
    const float wy = y - y0f;
    const int x0 = (int)x0f;
    const int y0 = (int)y0f;
    const int x1 = x0 + 1;
    const int y1 = y0 + 1;

    const bool vx0 = (x0 >= 0) && (x0 < WW);
    const bool vx1 = (x1 >= 0) && (x1 < WW);
    const bool vy0 = (y0 >= 0) && (y0 < HH);
    const bool vy1 = (y1 >= 0) && (y1 < HH);

    // fold validity into weights: invalid tap contributes exactly 0
    const float w00 = (vy0 && vx0) ? (1.0f - wy) * (1.0f - wx) : 0.0f;
    const float w01 = (vy0 && vx1) ? (1.0f - wy) * wx          : 0.0f;
    const float w10 = (vy1 && vx0) ? wy * (1.0f - wx)          : 0.0f;
    const float w11 = (vy1 && vx1) ? wy * wx                   : 0.0f;

    // clamped (always in-bounds) tap offsets within one channel plane
    const int xc0 = min(max(x0, 0), WW - 1);
    const int xc1 = min(max(x1, 0), WW - 1);
    const int yc0 = min(max(y0, 0), HH - 1);
    const int yc1 = min(max(y1, 0), HH - 1);

    const int o00 = yc0 * WW + xc0;
    const int o01 = yc0 * WW + xc1;
    const int o10 = yc1 * WW + xc0;
    const int o11 = yc1 * WW + xc1;

    const float* __restrict__ pb = in + (size_t)b * CC * HW;
    float* __restrict__ po = out + (size_t)b * CC * HOWO + (size_t)ho * WO + wo;

    #pragma unroll 8
    for (int c = 0; c < CC; ++c) {
        const float* pc = pb + c * HW;
        float v00 = __ldg(pc + o00);
        float v01 = __ldg(pc + o01);
        float v10 = __ldg(pc + o10);
        float v11 = __ldg(pc + o11);
        float v = w00 * v00;
        v = fmaf(w01, v01, v);
        v = fmaf(w10, v10, v);
        v = fmaf(w11, v11, v);
        po[(size_t)c * HOWO] = v;
    }
}

extern "C" void kernel_launch(void* const* d_in, const int* in_sizes, int n_in,
                              void* d_out, int out_size)
{
    const float* in   = (const float*)d_in[0];  // input   (8,128,128,128)
    const float* offx = (const float*)d_in[1];  // offset_x(8,1,256,256)
    const float* offy = (const float*)d_in[2];  // offset_y(8,1,256,256)
    float* out = (float*)d_out;                 // (8,128,256,256)

    const int total = BB * HO * WO;             // 524288 threads
    LaU_upsample_kernel<<<total / 256, 256>>>(in, offx, offy, out);
}

// round 17
// speedup vs baseline: 1.2718x; 1.2718x over previous
#include <cuda_runtime.h>

// Fixed problem shapes
#define BB   8
#define CC   128
#define HH   128
#define WW   128
#define HO   256
#define WO   256
#define HW   (HH * WW)       // 16384
#define HOWO (HO * WO)       // 65536

// 64 MB scratch: input transposed to NHWC  [b][y][x][c]
__device__ float g_nhwc[BB * HH * WW * CC];

// ---------------------------------------------------------------------------
// Kernel 1: NCHW -> NHWC transpose (32x32 smem tiles, fully coalesced)
// grid.x = 16 tiles (4 x-tiles * 4 c-tiles), grid.y = 1024 (b*128 + y)
// block = (32, 8); each thread handles 4 rows of the tile
// ---------------------------------------------------------------------------
__global__ __launch_bounds__(256)
void transpose_nchw_to_nhwc(const float* __restrict__ in)
{
    __shared__ float tile[32][33];

    const int xt = blockIdx.x & 3;          // x tile
    const int ct = blockIdx.x >> 2;         // c tile
    const int by = blockIdx.y;              // b*128 + y
    const int b  = by >> 7;
    const int y  = by & 127;

    const int tx = threadIdx.x;
    const int ty = threadIdx.y;

    // read: consecutive x -> coalesced
    #pragma unroll
    for (int j = 0; j < 4; ++j) {
        const int c = ct * 32 + ty + j * 8;
        const int x = xt * 32 + tx;
        tile[ty + j * 8][tx] = in[(((size_t)b * CC + c) * HH + y) * WW + x];
    }
    __syncthreads();

    // write: consecutive c -> coalesced
    #pragma unroll
    for (int j = 0; j < 4; ++j) {
        const int xw = xt * 32 + ty + j * 8;
        const int cw = ct * 32 + tx;
        g_nhwc[(((size_t)b * HH + y) * WW + xw) * CC + cw] = tile[tx][ty + j * 8];
    }
}

// ---------------------------------------------------------------------------
// Kernel 2: deformable 2x upsample.
// One WARP processes ONE output pixel across ALL 128 channels:
//   lane l holds channels [4l, 4l+3] as float4 -> every tap is one
//   fully-coalesced 512B LDG.128.
// Block = 256 threads = 8 warps = 32 consecutive wo pixels (4 px / warp).
// Results staged in smem [32 px][129] (conflict-free), then written to
// NCHW output with 128B-coalesced stores (lane = pixel, warp = channels).
// grid = 8b * 256ho * 8 wo-tiles = 16384 blocks
// ---------------------------------------------------------------------------
__global__ __launch_bounds__(256)
void LaU_upsample_nhwc_kernel(const float* __restrict__ offx,
                              const float* __restrict__ offy,
                              float* __restrict__ out)
{
    __shared__ float sres[32][129];   // [pixel][channel], stride 129 (conflict-free)

    const int warp = threadIdx.x >> 5;
    const int lane = threadIdx.x & 31;

    const int wo0 = (blockIdx.x & 7) << 5;          // 32-pixel tile base
    const int ho  = (blockIdx.x >> 3) & 255;
    const int b   = blockIdx.x >> 11;

    const float4* __restrict__ inb =
        (const float4*)(g_nhwc + (size_t)b * HW * CC);

    const float fy = 0.5f * (float)ho;

    #pragma unroll
    for (int k = 0; k < 4; ++k) {
        const int px = (warp << 2) + k;             // 0..31 within tile
        const int wo = wo0 + px;
        const int so = (b << 16) | (ho << 8) | wo;  // b*65536 + ho*256 + wo

        // broadcast loads (all lanes same address -> single sector)
        const float x = 0.5f * (float)wo + __ldg(offx + so);
        const float y = fy + __ldg(offy + so);

        const float x0f = floorf(x);
        const float y0f = floorf(y);
        const float wx = x - x0f;
        const float wy = y - y0f;
        const int x0 = (int)x0f, y0 = (int)y0f;
        const int x1 = x0 + 1,   y1 = y0 + 1;

        const bool vx0 = (x0 >= 0) && (x0 < WW);
        const bool vx1 = (x1 >= 0) && (x1 < WW);
        const bool vy0 = (y0 >= 0) && (y0 < HH);
        const bool vy1 = (y1 >= 0) && (y1 < HH);

        const float w00 = (vy0 && vx0) ? (1.0f - wy) * (1.0f - wx) : 0.0f;
        const float w01 = (vy0 && vx1) ? (1.0f - wy) * wx          : 0.0f;
        const float w10 = (vy1 && vx0) ? wy * (1.0f - wx)          : 0.0f;
        const float w11 = (vy1 && vx1) ? wy * wx                   : 0.0f;

        const int xc0 = min(max(x0, 0), WW - 1);
        const int xc1 = min(max(x1, 0), WW - 1);
        const int yc0 = min(max(y0, 0), HH - 1);
        const int yc1 = min(max(y1, 0), HH - 1);

        // float4 indices: ((y*WW + x)*CC)/4 + lane
        const int i00 = (yc0 * WW + xc0) * (CC / 4) + lane;
        const int i01 = (yc0 * WW + xc1) * (CC / 4) + lane;
        const int i10 = (yc1 * WW + xc0) * (CC / 4) + lane;
        const int i11 = (yc1 * WW + xc1) * (CC / 4) + lane;

        const float4 v00 = __ldg(inb + i00);
        const float4 v01 = __ldg(inb + i01);
        const float4 v10 = __ldg(inb + i10);
        const float4 v11 = __ldg(inb + i11);

        float4 acc;
        acc.x = fmaf(w11, v11.x, fmaf(w10, v10.x, fmaf(w01, v01.x, w00 * v00.x)));
        acc.y = fmaf(w11, v11.y, fmaf(w10, v10.y, fmaf(w01, v01.y, w00 * v00.y)));
        acc.z = fmaf(w11, v11.z, fmaf(w10, v10.z, fmaf(w01, v01.z, w00 * v00.z)));
        acc.w = fmaf(w11, v11.w, fmaf(w10, v10.w, fmaf(w01, v01.w, w00 * v00.w)));

        // scalar STS: bank (129*px + 4*lane + i) % 32 = (px + 5*lane + i) % 32
        // -> per-store, lanes hit 32 distinct banks (gcd(5,32)=1): conflict-free
        const int cb = lane << 2;
        sres[px][cb + 0] = acc.x;
        sres[px][cb + 1] = acc.y;
        sres[px][cb + 2] = acc.z;
        sres[px][cb + 3] = acc.w;
    }

    __syncthreads();

    // Output phase: warp w writes channels [16w, 16w+16), lane = pixel.
    // smem read bank: (129*lane + c) % 32 = (lane + c) % 32 -> conflict-free.
    // STG: consecutive lanes -> consecutive wo -> 128B coalesced.
    float* __restrict__ ob =
        out + ((size_t)b * CC) * HOWO + (size_t)ho * WO + wo0 + lane;

    const int c0 = warp << 4;
    #pragma unroll
    for (int i = 0; i < 16; ++i) {
        const int c = c0 + i;
        ob[(size_t)c * HOWO] = sres[lane][c];
    }
}

extern "C" void kernel_launch(void* const* d_in, const int* in_sizes, int n_in,
                              void* d_out, int out_size)
{
    const float* in   = (const float*)d_in[0];  // (8,128,128,128) NCHW
    const float* offx = (const float*)d_in[1];  // (8,1,256,256)
    const float* offy = (const float*)d_in[2];  // (8,1,256,256)
    float* out = (float*)d_out;                 // (8,128,256,256) NCHW

    {
        dim3 grid(16, BB * HH);
        dim3 block(32, 8);
        transpose_nchw_to_nhwc<<<grid, block>>>(in);
    }
    {
        const int nblocks = BB * HO * (WO / 32);   // 16384
        LaU_upsample_nhwc_kernel<<<nblocks, 256>>>(offx, offy, out);
    }
}